// round 11
// baseline (speedup 1.0000x reference)
#include <cuda_runtime.h>
#include <cstdint>

#define SEQ 2048
#define NB 64
#define NF 16
#define HD 512
#define ROWB 2048                        // bytes per hidden row (gmem)
#define SLOT_PAD 516                     // floats per f-row: 129 units ≡1 mod 8, conflict-free
#define MAX_G 128                        // max 16-token groups per batch (cnt <= 2048)
#define MAX_ITEMS (MAX_G * 4 * NB)       // item = g*256 + q*64 + b
#define GRID_X 444                       // 3 blocks/SM
#define NWARPS (GRID_X * 8)

// Scratch (allocation-free rule: __device__ globals)
__device__ int g_list[NB * SEQ];   // packed: token_pos | (seg << 16), compacted per batch
__device__ int g_cnt[NB];

__device__ __forceinline__ unsigned long long ffma2(unsigned long long a,
                                                    unsigned long long b,
                                                    unsigned long long c) {
    unsigned long long d;
    asm("fma.rn.f32x2 %0, %1, %2, %3;" : "=l"(d) : "l"(a), "l"(b), "l"(c));
    return d;
}

// ---------------------------------------------------------------------------
// Block-wide exclusive scan over 256 threads
// ---------------------------------------------------------------------------
__device__ __forceinline__ int block_exscan(int v, int* sh) {
    int lane = threadIdx.x & 31;
    int w = threadIdx.x >> 5;
    int incl = v;
#pragma unroll
    for (int o = 1; o < 32; o <<= 1) {
        int n = __shfl_up_sync(0xFFFFFFFFu, incl, o);
        if (lane >= o) incl += n;
    }
    if (lane == 31) sh[w] = incl;
    __syncthreads();
    if (threadIdx.x < 8) {
        int x = sh[threadIdx.x];
#pragma unroll
        for (int o = 1; o < 8; o <<= 1) {
            int n = __shfl_up_sync(0xFFu, x, o);
            if (threadIdx.x >= (unsigned)o) x += n;
        }
        sh[threadIdx.x] = x;
    }
    __syncthreads();
    int wofs = (w == 0) ? 0 : sh[w - 1];
    return wofs + incl - v;
}

// ---------------------------------------------------------------------------
// Kernel 1 (fused): zero output (all 256 blocks) + per-batch span ids +
// compaction (first 64 blocks).
// ---------------------------------------------------------------------------
__global__ __launch_bounds__(256) void seg_zero_kernel(const int* __restrict__ labels,
                                                       const int* pB, const int* pI,
                                                       const int* pMS,
                                                       float* __restrict__ out,
                                                       int out_n) {
    {
        int tid = blockIdx.x * 256 + threadIdx.x;
        int nthreads = gridDim.x * 256;
        int n4 = out_n >> 2;
        float4 z = make_float4(0.f, 0.f, 0.f, 0.f);
        for (int i = tid; i < n4; i += nthreads)
            reinterpret_cast<float4*>(out)[i] = z;
        for (int i = (n4 << 2) + tid; i < out_n; i += nthreads)
            out[i] = 0.0f;
    }
    if (blockIdx.x >= NB) return;

    __shared__ int sh[8];
    int b = blockIdx.x;
    int t = threadIdx.x;
    int Bv = pB ? *pB : 1;
    int Iv = pI ? *pI : 2;
    int MS = pMS ? *pMS : 512;

    const int4* row = reinterpret_cast<const int4*>(labels + b * SEQ) + t * 2;
    int4 a = row[0];
    int4 c = row[1];
    int lab[8] = {a.x, a.y, a.z, a.w, c.x, c.y, c.z, c.w};

    int incl[8];
    int csum = 0;
#pragma unroll
    for (int i = 0; i < 8; i++) {
        csum += (lab[i] == Bv);
        incl[i] = csum;
    }
    int ex = block_exscan(csum, sh);

    int seg[8], vfl[8];
    int vtot = 0;
#pragma unroll
    for (int i = 0; i < 8; i++) {
        seg[i] = ex + incl[i] - 1;
        vfl[i] = ((lab[i] == Bv) || (lab[i] == Iv)) && seg[i] >= 0 && seg[i] < MS;
        vtot += vfl[i];
    }
    __syncthreads();
    int vex = block_exscan(vtot, sh);

    int pos = vex;
#pragma unroll
    for (int i = 0; i < 8; i++) {
        if (vfl[i]) {
            g_list[b * SEQ + pos] = (t * 8 + i) | (seg[i] << 16);
            pos++;
        }
    }
    if (t == 255) g_cnt[b] = vex + vtot;
}

// ---------------------------------------------------------------------------
// Kernel 2: DIRECT-LDG gather-projection (no smem staging, no pipeline).
//
// Work item = (16-token group g of batch b, d-quarter q), item = g*256+q*64+b
// (g-major: valid items dense at the bottom). Warps grid-stride over items.
//
// Lane (tg = l>>3, fh = l&7) owns tokens {tg+4j} x f = {fh, fh+8}.
// Inner loop over 32 d-chunks (16B): 4 H LDG.128 (each instr: 4 distinct
// token rows, 8-lane broadcast -> nL=4; consecutive chunks hit the same L1
// line) + 2 S LDS.128 (conflict-free) -> 16 FFMA2. ptxas free to batch LDGs
// across the unroll window: MLP >> ring-depth-3 of the staged designs, and
// zero cp_wait/syncwarp serialization.
//
// Quarter-d partial sums scatter via atomicAdd.
// ---------------------------------------------------------------------------
__global__ __launch_bounds__(256, 3) void proj_kernel(const float* __restrict__ hidden,
                                                      const float* __restrict__ slot,
                                                      const int* pMS,
                                                      float* __restrict__ out) {
    __shared__ float slot_sh[NF * SLOT_PAD];
    __shared__ int cnts[NB];
    int MS = pMS ? *pMS : 512;

    // stage slot_embs transposed: slot_sh[f][d]; cache per-batch counts
    for (int i = threadIdx.x; i < HD * NF; i += 256) {
        int d = i >> 4;
        int f = i & 15;
        slot_sh[f * SLOT_PAD + d] = slot[i];
    }
    if (threadIdx.x < NB) cnts[threadIdx.x] = g_cnt[threadIdx.x];
    __syncthreads();

    int w = threadIdx.x >> 5;
    int lane = threadIdx.x & 31;
    int tg = lane >> 3;       // token group (0..3)
    int fh = lane & 7;        // f half (0..7)

    const char* hbytes = reinterpret_cast<const char*>(hidden);
    int wid = blockIdx.x * 8 + w;

    for (int item = wid; item < MAX_ITEMS; item += NWARPS) {
        int g = item >> 8;
        int q = (item >> 6) & 3;
        int b = item & 63;
        int cnt = cnts[b];
        int t0 = g * 16;
        if (t0 >= cnt) continue;   // warp-uniform

        const int* lst = g_list + b * SEQ;

        // per-lane: row byte-offsets + packed entries for this lane's 4 tokens
        unsigned ro[4];
        int pk[4];
        bool val[4];
#pragma unroll
        for (int j = 0; j < 4; j++) {
            int ti = t0 + tg + 4 * j;
            val[j] = ti < cnt;
            if (ti >= cnt) ti = cnt - 1;
            int p = lst[ti];
            pk[j] = p;
            ro[j] = ((unsigned)b * SEQ + (unsigned)(p & 0xFFFF)) * ROWB + q * 512;
        }

        const float* s0p = slot_sh + fh * SLOT_PAD + q * 128;
        const float* s1p = s0p + 8 * SLOT_PAD;

        unsigned long long acc[4][2];
#pragma unroll
        for (int j = 0; j < 4; j++) {
            acc[j][0] = 0ull;
            acc[j][1] = 0ull;
        }

#pragma unroll 8
        for (int c = 0; c < 32; c++) {
            ulonglong2 S0 = *reinterpret_cast<const ulonglong2*>(s0p + c * 4);
            ulonglong2 S1 = *reinterpret_cast<const ulonglong2*>(s1p + c * 4);
#pragma unroll
            for (int j = 0; j < 4; j++) {
                ulonglong2 H = *reinterpret_cast<const ulonglong2*>(hbytes + ro[j] + c * 16);
                acc[j][0] = ffma2(H.x, S0.x, acc[j][0]);
                acc[j][0] = ffma2(H.y, S0.y, acc[j][0]);
                acc[j][1] = ffma2(H.x, S1.x, acc[j][1]);
                acc[j][1] = ffma2(H.y, S1.y, acc[j][1]);
            }
        }

#pragma unroll
        for (int j = 0; j < 4; j++) {
            if (val[j]) {
                float* op = out + ((size_t)b * MS + (pk[j] >> 16)) * NF;
                float2 v0 = *reinterpret_cast<float2*>(&acc[j][0]);
                float2 v1 = *reinterpret_cast<float2*>(&acc[j][1]);
                atomicAdd(op + fh, v0.x + v0.y);
                atomicAdd(op + fh + 8, v1.x + v1.y);
            }
        }
    }
}

// ---------------------------------------------------------------------------
extern "C" void kernel_launch(void* const* d_in, const int* in_sizes, int n_in,
                              void* d_out, int out_size) {
    const float* hidden = (const float*)d_in[0];
    const float* slot = (const float*)d_in[1];
    const int* labels = (const int*)d_in[2];
    const int* pB = (n_in > 3) ? (const int*)d_in[3] : nullptr;
    const int* pI = (n_in > 4) ? (const int*)d_in[4] : nullptr;
    const int* pMS = (n_in > 5) ? (const int*)d_in[5] : nullptr;
    float* out = (float*)d_out;

    seg_zero_kernel<<<256, 256>>>(labels, pB, pI, pMS, out, out_size);
    proj_kernel<<<GRID_X, 256>>>(hidden, slot, pMS, out);
}

// round 12
// speedup vs baseline: 1.1146x; 1.1146x over previous
#include <cuda_runtime.h>
#include <cstdint>

#define SEQ 2048
#define NB 64
#define NF 16
#define HD 512
#define ROWB 2048                        // bytes per hidden row (gmem)
#define SLOT_PAD 516                     // floats per f-row: 129 units ≡1 mod 8, conflict-free
#define SLOT_BYTES (NF * SLOT_PAD * 4)   // 33024
#define TROW 144                         // staged token-row stride (9 units ≡1 mod 8)
#define STAGE_B (16 * TROW)              // 2304: 16 tok x 32 d
#define RING_STAGES 6
#define NW 4                             // warps per block
#define SMEM_TOTAL (SLOT_BYTES + NW * RING_STAGES * STAGE_B + NB * 4)  // 88576 -> 2 blocks/SM
#define CNT_OFF (SLOT_BYTES + NW * RING_STAGES * STAGE_B)
#define MAX_G 128
#define MAX_ITEMS (MAX_G * 4 * NB)       // item = g*256 + q*64 + b (g-major)
#define GRID_X 296                       // 2 blocks/SM
#define NWARPS (GRID_X * NW)             // 1184

// Scratch (allocation-free rule: __device__ globals)
__device__ int g_list[NB * SEQ];   // packed: token_pos | (seg << 16), compacted per batch
__device__ int g_cnt[NB];

__device__ __forceinline__ unsigned long long ffma2(unsigned long long a,
                                                    unsigned long long b,
                                                    unsigned long long c) {
    unsigned long long d;
    asm("fma.rn.f32x2 %0, %1, %2, %3;" : "=l"(d) : "l"(a), "l"(b), "l"(c));
    return d;
}

__device__ __forceinline__ void cp16(void* dst_smem, const void* src) {
    unsigned saddr = (unsigned)__cvta_generic_to_shared(dst_smem);
    asm volatile("cp.async.cg.shared.global [%0], [%1], 16;" :: "r"(saddr), "l"(src));
}
__device__ __forceinline__ void cp_commit() {
    asm volatile("cp.async.commit_group;");
}
template <int N>
__device__ __forceinline__ void cp_wait() {
    asm volatile("cp.async.wait_group %0;" :: "n"(N));
}

// ---------------------------------------------------------------------------
// Block-wide exclusive scan over 256 threads
// ---------------------------------------------------------------------------
__device__ __forceinline__ int block_exscan(int v, int* sh) {
    int lane = threadIdx.x & 31;
    int w = threadIdx.x >> 5;
    int incl = v;
#pragma unroll
    for (int o = 1; o < 32; o <<= 1) {
        int n = __shfl_up_sync(0xFFFFFFFFu, incl, o);
        if (lane >= o) incl += n;
    }
    if (lane == 31) sh[w] = incl;
    __syncthreads();
    if (threadIdx.x < 8) {
        int x = sh[threadIdx.x];
#pragma unroll
        for (int o = 1; o < 8; o <<= 1) {
            int n = __shfl_up_sync(0xFFu, x, o);
            if (threadIdx.x >= (unsigned)o) x += n;
        }
        sh[threadIdx.x] = x;
    }
    __syncthreads();
    int wofs = (w == 0) ? 0 : sh[w - 1];
    return wofs + incl - v;
}

// ---------------------------------------------------------------------------
// Kernel 1 (fused): zero output (all 256 blocks) + per-batch span ids +
// compaction (first 64 blocks).
// ---------------------------------------------------------------------------
__global__ __launch_bounds__(256) void seg_zero_kernel(const int* __restrict__ labels,
                                                       const int* pB, const int* pI,
                                                       const int* pMS,
                                                       float* __restrict__ out,
                                                       int out_n) {
    {
        int tid = blockIdx.x * 256 + threadIdx.x;
        int nthreads = gridDim.x * 256;
        int n4 = out_n >> 2;
        float4 z = make_float4(0.f, 0.f, 0.f, 0.f);
        for (int i = tid; i < n4; i += nthreads)
            reinterpret_cast<float4*>(out)[i] = z;
        for (int i = (n4 << 2) + tid; i < out_n; i += nthreads)
            out[i] = 0.0f;
    }
    if (blockIdx.x >= NB) return;

    __shared__ int sh[8];
    int b = blockIdx.x;
    int t = threadIdx.x;
    int Bv = pB ? *pB : 1;
    int Iv = pI ? *pI : 2;
    int MS = pMS ? *pMS : 512;

    const int4* row = reinterpret_cast<const int4*>(labels + b * SEQ) + t * 2;
    int4 a = row[0];
    int4 c = row[1];
    int lab[8] = {a.x, a.y, a.z, a.w, c.x, c.y, c.z, c.w};

    int incl[8];
    int csum = 0;
#pragma unroll
    for (int i = 0; i < 8; i++) {
        csum += (lab[i] == Bv);
        incl[i] = csum;
    }
    int ex = block_exscan(csum, sh);

    int seg[8], vfl[8];
    int vtot = 0;
#pragma unroll
    for (int i = 0; i < 8; i++) {
        seg[i] = ex + incl[i] - 1;
        vfl[i] = ((lab[i] == Bv) || (lab[i] == Iv)) && seg[i] >= 0 && seg[i] < MS;
        vtot += vfl[i];
    }
    __syncthreads();
    int vex = block_exscan(vtot, sh);

    int pos = vex;
#pragma unroll
    for (int i = 0; i < 8; i++) {
        if (vfl[i]) {
            g_list[b * SEQ + pos] = (t * 8 + i) | (seg[i] << 16);
            pos++;
        }
    }
    if (t == 255) g_cnt[b] = vex + vtot;
}

// ---------------------------------------------------------------------------
// Kernel 2: warp-autonomous gather-projection, 6-deep ring, issue-ahead 5.
//
// Warp item = (16-token group g of batch b, d-quarter q). Item = 4 stages of
// 16 tok x 32 d (2304 B staged, linear 144B rows). 4-warp blocks so smem
// affords a 6-slot ring per warp: cover = 5 stages >> loaded DRAM latency.
//
// Staging: lane (r4, qq) covers tokens {r4, r4+8}, chunks {qq, qq+4} ->
// 4 cp16/stage (each warp instr: 8 rows x 64B).
// Compute: lane (tg, fh) tiles tokens {tg+4j} x f={fh, fh+8}; all LDS
// offsets base+const; banks conflict-free (rows ≡1 mod 8 units).
// Quarter-d partial sums scatter via atomicAdd.
// ---------------------------------------------------------------------------
__global__ __launch_bounds__(128, 2) void proj_kernel(const float* __restrict__ hidden,
                                                      const float* __restrict__ slot,
                                                      const int* pMS,
                                                      float* __restrict__ out) {
    extern __shared__ float smem[];
    float* slot_sh = smem;
    char* ringbase = reinterpret_cast<char*>(smem) + SLOT_BYTES;
    int* cnts = reinterpret_cast<int*>(reinterpret_cast<char*>(smem) + CNT_OFF);
    int MS = pMS ? *pMS : 512;

    // stage slot_embs transposed (vectorized): slot[d][f] -> slot_sh[f][d]
    for (int i = threadIdx.x; i < (HD * NF) / 4; i += 128) {
        int d = i >> 2;
        int f4 = (i & 3) * 4;
        float4 v = reinterpret_cast<const float4*>(slot)[i];
        slot_sh[(f4 + 0) * SLOT_PAD + d] = v.x;
        slot_sh[(f4 + 1) * SLOT_PAD + d] = v.y;
        slot_sh[(f4 + 2) * SLOT_PAD + d] = v.z;
        slot_sh[(f4 + 3) * SLOT_PAD + d] = v.w;
    }
    if (threadIdx.x < NB) cnts[threadIdx.x] = g_cnt[threadIdx.x];
    __syncthreads();

    int w = threadIdx.x >> 5;
    int lane = threadIdx.x & 31;
    int r4 = lane >> 2;       // staging token group (0..7)
    int qq = lane & 3;        // staging chunk quad (0..3)
    int tg = lane >> 3;       // compute token base (0..3)
    int fh = lane & 7;        // compute f half (0..7)
    char* ring0 = ringbase + w * RING_STAGES * STAGE_B;
    char* ring_end = ring0 + RING_STAGES * STAGE_B;

    int dstA[2], dstB[2];
#pragma unroll
    for (int m = 0; m < 2; m++) {
        dstA[m] = (r4 + 8 * m) * TROW + qq * 16;
        dstB[m] = dstA[m] + 64;
    }

    const char* hbytes = reinterpret_cast<const char*>(hidden);
    int wid = blockIdx.x * NW + w;

    // count this warp's valid items -> total stages
    int nitems = 0;
    for (int it = wid; it < MAX_ITEMS; it += NWARPS)
        if ((it >> 8) * 16 < cnts[it & 63]) nitems++;
    if (nitems == 0) return;
    int total = nitems * 4;

    auto next_valid = [&](int it) {
        while (it < MAX_ITEMS && (it >> 8) * 16 >= cnts[it & 63]) it += NWARPS;
        return it;
    };

    // ---- issue cursor ----
    int it_i = next_valid(wid);
    int s_i = 0;
    int isl = 0;
    char* buf_i = ring0;
    unsigned ofs_i[2];

    auto load_ofs = [&](int it) {
        int g = it >> 8;
        int q = (it >> 6) & 3;
        int b = it & 63;
        int cnt = cnts[b];
        int t0 = g * 16;
#pragma unroll
        for (int m = 0; m < 2; m++) {
            int ti = t0 + r4 + 8 * m;
            if (ti >= cnt) ti = cnt - 1;
            ofs_i[m] = ((unsigned)b * SEQ + (unsigned)(g_list[b * SEQ + ti] & 0xFFFF)) * ROWB
                       + (unsigned)q * 512;
        }
    };
    load_ofs(it_i);

    auto issue_one = [&]() {
#pragma unroll
        for (int m = 0; m < 2; m++) {
            const char* src = hbytes + ofs_i[m] + s_i * 128;
            cp16(buf_i + dstA[m], src + qq * 16);
            cp16(buf_i + dstB[m], src + qq * 16 + 64);
        }
        cp_commit();
        isl++;
        buf_i += STAGE_B;
        if (buf_i == ring_end) buf_i = ring0;
        if (++s_i == 4) {
            s_i = 0;
            it_i = next_valid(it_i + NWARPS);
            if (it_i < MAX_ITEMS) load_ofs(it_i);
        }
    };

    int pre = total < 5 ? total : 5;
    for (int k = 0; k < pre; k++) issue_one();

    // ---- compute cursor ----
    int it_c = next_valid(wid);
    char* buf_c = ring0;

    unsigned long long acc[4][2];

    for (int i = 0; i < total; i++) {
        int pending = isl - i;       // groups not yet known-complete incl. this one
        if (pending >= 5) cp_wait<4>();
        else if (pending == 4) cp_wait<3>();
        else if (pending == 3) cp_wait<2>();
        else if (pending == 2) cp_wait<1>();
        else cp_wait<0>();
        __syncwarp();

        int s = i & 3;
        if (s == 0) {
#pragma unroll
            for (int j = 0; j < 4; j++) {
                acc[j][0] = 0ull;
                acc[j][1] = 0ull;
            }
        }

        int q = (it_c >> 6) & 3;
        const char* hb = buf_c + tg * TROW;
        const float* s0p = slot_sh + fh * SLOT_PAD + q * 128 + s * 32;
        const float* s1p = s0p + 8 * SLOT_PAD;
#pragma unroll
        for (int c = 0; c < 8; c++) {
            ulonglong2 S0 = *reinterpret_cast<const ulonglong2*>(s0p + c * 4);
            ulonglong2 S1 = *reinterpret_cast<const ulonglong2*>(s1p + c * 4);
#pragma unroll
            for (int j = 0; j < 4; j++) {
                ulonglong2 H = *reinterpret_cast<const ulonglong2*>(hb + j * (4 * TROW) + c * 16);
                acc[j][0] = ffma2(H.x, S0.x, acc[j][0]);
                acc[j][0] = ffma2(H.y, S0.y, acc[j][0]);
                acc[j][1] = ffma2(H.x, S1.x, acc[j][1]);
                acc[j][1] = ffma2(H.y, S1.y, acc[j][1]);
            }
        }

        if (s == 3) {
            int g = it_c >> 8;
            int b = it_c & 63;
            int cnt = cnts[b];
            int t0 = g * 16;
            const int* lst = g_list + b * SEQ;
#pragma unroll
            for (int j = 0; j < 4; j++) {
                int ti = t0 + tg + 4 * j;
                if (ti < cnt) {
                    int p = lst[ti];
                    float* op = out + ((size_t)b * MS + (p >> 16)) * NF;
                    float2 v0 = *reinterpret_cast<float2*>(&acc[j][0]);
                    float2 v1 = *reinterpret_cast<float2*>(&acc[j][1]);
                    atomicAdd(op + fh, v0.x + v0.y);
                    atomicAdd(op + fh + 8, v1.x + v1.y);
                }
            }
            it_c = next_valid(it_c + NWARPS);
        }

        buf_c += STAGE_B;
        if (buf_c == ring_end) buf_c = ring0;

        __syncwarp();   // ring slot fully read before refill
        if (isl < total) issue_one();
    }
}

// ---------------------------------------------------------------------------
extern "C" void kernel_launch(void* const* d_in, const int* in_sizes, int n_in,
                              void* d_out, int out_size) {
    const float* hidden = (const float*)d_in[0];
    const float* slot = (const float*)d_in[1];
    const int* labels = (const int*)d_in[2];
    const int* pB = (n_in > 3) ? (const int*)d_in[3] : nullptr;
    const int* pI = (n_in > 4) ? (const int*)d_in[4] : nullptr;
    const int* pMS = (n_in > 5) ? (const int*)d_in[5] : nullptr;
    float* out = (float*)d_out;

    static bool attr_set = false;
    if (!attr_set) {
        cudaFuncSetAttribute(proj_kernel, cudaFuncAttributeMaxDynamicSharedMemorySize,
                             SMEM_TOTAL);
        attr_set = true;
    }

    seg_zero_kernel<<<256, 256>>>(labels, pB, pI, pMS, out, out_size);
    proj_kernel<<<GRID_X, 128, SMEM_TOTAL>>>(hidden, slot, pMS, out);
}

// round 13
// speedup vs baseline: 1.2685x; 1.1380x over previous
#include <cuda_runtime.h>
#include <cstdint>

#define SEQ 2048
#define NB 64
#define NF 16
#define HD 512
#define ROWB 2048                        // bytes per hidden row (gmem)
#define SLOT_PAD 516                     // floats per f-row: 129 units ≡1 mod 8, conflict-free
#define SLOT_BYTES (NF * SLOT_PAD * 4)   // 33024
#define TROW 272                         // staged token-row stride (17 units ≡1 mod 8)
#define STAGE_B (16 * TROW)              // 4352: 16 tok x 64 d
#define RING 3
#define NPAIR 4                          // producer/consumer pairs per block
#define RING_BYTES (NPAIR * RING * STAGE_B)   // 52224
#define CNT_OFF (SLOT_BYTES + RING_BYTES)     // 85248
#define SMEM_TOTAL (CNT_OFF + NB * 4)         // 85504 -> 2 blocks/SM
#define MAX_G 128
#define MAX_ITEMS (MAX_G * NB)           // item = g*64 + b (g-major: valid items dense)
#define GRID_X 296                       // 2 blocks/SM

// Scratch (allocation-free rule: __device__ globals)
__device__ int g_list[NB * SEQ];   // packed: token_pos | (seg << 16), compacted per batch
__device__ int g_cnt[NB];

__device__ __forceinline__ unsigned long long ffma2(unsigned long long a,
                                                    unsigned long long b,
                                                    unsigned long long c) {
    unsigned long long d;
    asm("fma.rn.f32x2 %0, %1, %2, %3;" : "=l"(d) : "l"(a), "l"(b), "l"(c));
    return d;
}

__device__ __forceinline__ void cp16(void* dst_smem, const void* src) {
    unsigned saddr = (unsigned)__cvta_generic_to_shared(dst_smem);
    asm volatile("cp.async.cg.shared.global [%0], [%1], 16;" :: "r"(saddr), "l"(src));
}
__device__ __forceinline__ void cp_commit() {
    asm volatile("cp.async.commit_group;");
}
template <int N>
__device__ __forceinline__ void cp_wait() {
    asm volatile("cp.async.wait_group %0;" :: "n"(N));
}
__device__ __forceinline__ void pair_bar(int id) {
    asm volatile("bar.sync %0, 64;" :: "r"(id) : "memory");
}

// ---------------------------------------------------------------------------
// Block-wide exclusive scan over 256 threads
// ---------------------------------------------------------------------------
__device__ __forceinline__ int block_exscan(int v, int* sh) {
    int lane = threadIdx.x & 31;
    int w = threadIdx.x >> 5;
    int incl = v;
#pragma unroll
    for (int o = 1; o < 32; o <<= 1) {
        int n = __shfl_up_sync(0xFFFFFFFFu, incl, o);
        if (lane >= o) incl += n;
    }
    if (lane == 31) sh[w] = incl;
    __syncthreads();
    if (threadIdx.x < 8) {
        int x = sh[threadIdx.x];
#pragma unroll
        for (int o = 1; o < 8; o <<= 1) {
            int n = __shfl_up_sync(0xFFu, x, o);
            if (threadIdx.x >= (unsigned)o) x += n;
        }
        sh[threadIdx.x] = x;
    }
    __syncthreads();
    int wofs = (w == 0) ? 0 : sh[w - 1];
    return wofs + incl - v;
}

// ---------------------------------------------------------------------------
// Kernel 1 (fused): zero output (all 256 blocks) + per-batch span ids +
// compaction (first 64 blocks).
// ---------------------------------------------------------------------------
__global__ __launch_bounds__(256) void seg_zero_kernel(const int* __restrict__ labels,
                                                       const int* pB, const int* pI,
                                                       const int* pMS,
                                                       float* __restrict__ out,
                                                       int out_n) {
    {
        int tid = blockIdx.x * 256 + threadIdx.x;
        int nthreads = gridDim.x * 256;
        int n4 = out_n >> 2;
        float4 z = make_float4(0.f, 0.f, 0.f, 0.f);
        for (int i = tid; i < n4; i += nthreads)
            reinterpret_cast<float4*>(out)[i] = z;
        for (int i = (n4 << 2) + tid; i < out_n; i += nthreads)
            out[i] = 0.0f;
    }
    if (blockIdx.x >= NB) return;

    __shared__ int sh[8];
    int b = blockIdx.x;
    int t = threadIdx.x;
    int Bv = pB ? *pB : 1;
    int Iv = pI ? *pI : 2;
    int MS = pMS ? *pMS : 512;

    const int4* row = reinterpret_cast<const int4*>(labels + b * SEQ) + t * 2;
    int4 a = row[0];
    int4 c = row[1];
    int lab[8] = {a.x, a.y, a.z, a.w, c.x, c.y, c.z, c.w};

    int incl[8];
    int csum = 0;
#pragma unroll
    for (int i = 0; i < 8; i++) {
        csum += (lab[i] == Bv);
        incl[i] = csum;
    }
    int ex = block_exscan(csum, sh);

    int seg[8], vfl[8];
    int vtot = 0;
#pragma unroll
    for (int i = 0; i < 8; i++) {
        seg[i] = ex + incl[i] - 1;
        vfl[i] = ((lab[i] == Bv) || (lab[i] == Iv)) && seg[i] >= 0 && seg[i] < MS;
        vtot += vfl[i];
    }
    __syncthreads();
    int vex = block_exscan(vtot, sh);

    int pos = vex;
#pragma unroll
    for (int i = 0; i < 8; i++) {
        if (vfl[i]) {
            g_list[b * SEQ + pos] = (t * 8 + i) | (seg[i] << 16);
            pos++;
        }
    }
    if (t == 255) g_cnt[b] = vex + vtot;
}

// ---------------------------------------------------------------------------
// Kernel 2: WARP-SPECIALIZED gather-projection.
//
// Block = 4 (producer, consumer) pairs. Pair p owns d-quarter q=p of every
// block item (16 compacted tokens of batch b; item = g*64+b, block strides
// GRID_X). Item = 2 stages of 16 tok x 64 d (4352 B, rows 272 B).
//
// Producer (wid 4+p): per stage, 8 cp16 warp-instrs (2 full 256B row-quarters
// each, coalesced) into a 3-slot ring. Step i: issue stage i+2, wait_group<1>
// (stage i+1 landed), bar. Eats ALL global latency.
//
// Consumer (wid p): lane (tg, fh) tiles tokens {tg+4j} x f={fh,fh+8}; per
// 16B chunk 2 S + 4 H LDS.128 (conflict-free) -> 16 FFMA2. Step i: compute
// stage i, scatter at item end (packed entries via shfl), bar. Never issues
// a global load in the mainloop.
// ---------------------------------------------------------------------------
__global__ __launch_bounds__(256, 2) void proj_kernel(const float* __restrict__ hidden,
                                                      const float* __restrict__ slot,
                                                      const int* pMS,
                                                      float* __restrict__ out) {
    extern __shared__ float smem[];
    float* slot_sh = smem;
    char* ringbase = reinterpret_cast<char*>(smem) + SLOT_BYTES;
    int* cnts = reinterpret_cast<int*>(reinterpret_cast<char*>(smem) + CNT_OFF);
    int MS = pMS ? *pMS : 512;

    // stage slot_embs transposed (vectorized): slot[d][f] -> slot_sh[f][d]
    for (int i = threadIdx.x; i < (HD * NF) / 4; i += 256) {
        int d = i >> 2;
        int f4 = (i & 3) * 4;
        float4 v = reinterpret_cast<const float4*>(slot)[i];
        slot_sh[(f4 + 0) * SLOT_PAD + d] = v.x;
        slot_sh[(f4 + 1) * SLOT_PAD + d] = v.y;
        slot_sh[(f4 + 2) * SLOT_PAD + d] = v.z;
        slot_sh[(f4 + 3) * SLOT_PAD + d] = v.w;
    }
    if (threadIdx.x < NB) cnts[threadIdx.x] = g_cnt[threadIdx.x];
    __syncthreads();

    int w = threadIdx.x >> 5;
    int lane = threadIdx.x & 31;
    int pair = w & 3;
    int q = pair;                         // d-quarter
    bool producer = w >= 4;
    char* ring0 = ringbase + pair * RING * STAGE_B;
    int barid = 1 + pair;

    // count this block's valid items
    int nitems = 0;
    for (int it = blockIdx.x; it < MAX_ITEMS; it += GRID_X)
        if ((it >> 6) * 16 < cnts[it & 63]) nitems++;
    if (nitems == 0) return;
    int T = nitems * 2;

    auto next_valid = [&](int it) {
        while (it < MAX_ITEMS && (it >> 6) * 16 >= cnts[it & 63]) it += GRID_X;
        return it;
    };

    if (producer) {
        const char* hbytes = reinterpret_cast<const char*>(hidden);
        int it = next_valid(blockIdx.x);
        unsigned ofs_lane = 0;   // lane l holds row offset for token (l&15)
        int half = 0;
        int issued = 0;

        auto load_item = [&]() {
            int g = it >> 6;
            int b = it & 63;
            int cnt = cnts[b];
            int ti = g * 16 + (lane & 15);
            if (ti >= cnt) ti = cnt - 1;
            ofs_lane = ((unsigned)b * SEQ + (unsigned)(g_list[b * SEQ + ti] & 0xFFFF)) * ROWB
                       + (unsigned)q * 512;
        };
        load_item();

        auto issue_one = [&]() {
            char* buf = ring0 + (issued % RING) * STAGE_B;
            unsigned sub = (unsigned)half * 256 + (unsigned)(lane & 15) * 16;
            int dofs = (lane & 15) * 16;
#pragma unroll
            for (int j = 0; j < 8; j++) {
                int r = 2 * j + (lane >> 4);
                unsigned ro = __shfl_sync(0xFFFFFFFFu, ofs_lane, r);
                cp16(buf + r * TROW + dofs, hbytes + ro + sub);
            }
            cp_commit();
            issued++;
            if (++half == 2) {
                half = 0;
                it = next_valid(it + GRID_X);
                if (it < MAX_ITEMS) load_item();
            }
        };

        issue_one();
        if (T > 1) {
            issue_one();
            cp_wait<1>();
        } else {
            cp_wait<0>();
        }
        pair_bar(barid);                       // stage 0 ready
        for (int i = 0; i < T; i++) {
            if (i + 2 < T) {
                issue_one();
                cp_wait<1>();                  // stage i+1 landed
            } else {
                cp_wait<0>();
            }
            pair_bar(barid);
        }
    } else {
        int tg = lane >> 3;       // token base (0..3); tokens tg+4j
        int fh = lane & 7;        // f half (0..7)
        int it = next_valid(blockIdx.x);
        int pkc = 0, cnt = 0, t0 = 0, b = 0;

        auto load_item = [&]() {
            int g = it >> 6;
            b = it & 63;
            cnt = cnts[b];
            t0 = g * 16;
            int ti = t0 + (lane & 15);
            if (ti >= cnt) ti = cnt - 1;
            pkc = g_list[b * SEQ + ti];   // lane l holds packed entry of token (l&15)
        };
        load_item();

        const float* sbase = slot_sh + fh * SLOT_PAD + q * 128;
        unsigned long long acc[4][2];

        pair_bar(barid);                       // stage 0 ready
        for (int i = 0; i < T; i++) {
            int halfv = i & 1;
            const char* buf = ring0 + (i % RING) * STAGE_B + tg * TROW;
            if (halfv == 0) {
#pragma unroll
                for (int j = 0; j < 4; j++) {
                    acc[j][0] = 0ull;
                    acc[j][1] = 0ull;
                }
            }
            const float* s0p = sbase + halfv * 64;
            const float* s1p = s0p + 8 * SLOT_PAD;
#pragma unroll
            for (int c = 0; c < 16; c++) {
                ulonglong2 S0 = *reinterpret_cast<const ulonglong2*>(s0p + c * 4);
                ulonglong2 S1 = *reinterpret_cast<const ulonglong2*>(s1p + c * 4);
#pragma unroll
                for (int j = 0; j < 4; j++) {
                    ulonglong2 H = *reinterpret_cast<const ulonglong2*>(buf + j * (4 * TROW) + c * 16);
                    acc[j][0] = ffma2(H.x, S0.x, acc[j][0]);
                    acc[j][0] = ffma2(H.y, S0.y, acc[j][0]);
                    acc[j][1] = ffma2(H.x, S1.x, acc[j][1]);
                    acc[j][1] = ffma2(H.y, S1.y, acc[j][1]);
                }
            }
            if (halfv == 1) {
#pragma unroll
                for (int j = 0; j < 4; j++) {
                    int tok = tg + 4 * j;
                    int p = __shfl_sync(0xFFFFFFFFu, pkc, tok);
                    if (t0 + tok < cnt) {
                        float* op = out + ((size_t)b * MS + (p >> 16)) * NF;
                        float2 v0 = *reinterpret_cast<float2*>(&acc[j][0]);
                        float2 v1 = *reinterpret_cast<float2*>(&acc[j][1]);
                        atomicAdd(op + fh, v0.x + v0.y);
                        atomicAdd(op + fh + 8, v1.x + v1.y);
                    }
                }
                it = next_valid(it + GRID_X);
                if (it < MAX_ITEMS) load_item();
            }
            pair_bar(barid);                   // stage i consumed
        }
    }
}

// ---------------------------------------------------------------------------
extern "C" void kernel_launch(void* const* d_in, const int* in_sizes, int n_in,
                              void* d_out, int out_size) {
    const float* hidden = (const float*)d_in[0];
    const float* slot = (const float*)d_in[1];
    const int* labels = (const int*)d_in[2];
    const int* pB = (n_in > 3) ? (const int*)d_in[3] : nullptr;
    const int* pI = (n_in > 4) ? (const int*)d_in[4] : nullptr;
    const int* pMS = (n_in > 5) ? (const int*)d_in[5] : nullptr;
    float* out = (float*)d_out;

    static bool attr_set = false;
    if (!attr_set) {
        cudaFuncSetAttribute(proj_kernel, cudaFuncAttributeMaxDynamicSharedMemorySize,
                             SMEM_TOTAL);
        attr_set = true;
    }

    seg_zero_kernel<<<256, 256>>>(labels, pB, pI, pMS, out, out_size);
    proj_kernel<<<GRID_X, 256, SMEM_TOTAL>>>(hidden, slot, pMS, out);
}